// round 2
// baseline (speedup 1.0000x reference)
#include <cuda_runtime.h>
#include <float.h>

#define BB 64
#define LL 8192
#define DD 64
#define NSPLIT 16
#define CHUNK (LL / NSPLIT)   // 512

// Scratch (device mallocs forbidden)
__device__ float g_partial_acc[BB * NSPLIT * DD];
__device__ float g_partial_m[BB * NSPLIT];
__device__ float g_partial_s[BB * NSPLIT];

// ---------------------------------------------------------------------------
// Kernel A: per (batch, chunk) — logits + softmax partials + partial
// exp-weighted v accumulation. Reads kc and v exactly once each.
// grid (NSPLIT, B), 256 threads.
// ---------------------------------------------------------------------------
__global__ void __launch_bounds__(256)
collect_partials_kernel(const float* __restrict__ q,
                        const float* __restrict__ kc,
                        const float* __restrict__ v,
                        const float* __restrict__ tc,
                        float* __restrict__ out_logit)
{
    __shared__ float4 q4_sh[16];
    __shared__ float  logit_sh[CHUNK];   // reused later for exp-weights
    __shared__ float  red[256];

    const int t = threadIdx.x;
    const int c = blockIdx.x;
    const int b = blockIdx.y;
    const int row0 = c * CHUNK;

    if (t < 16) q4_sh[t] = ((const float4*)(q + b * DD))[t];
    __syncthreads();

    const float inv_tc = 1.0f / *tc;

    // ---- Pass 1: logits (also the required logit output) + local max ----
    const float4* kc4 = (const float4*)(kc + (size_t)b * LL * DD);
    float lmax = -FLT_MAX;
    const int seg  = t & 15;          // 16 float4 segments per 64-float row
    const int rsub = t >> 4;          // 16 rows per iteration

    #pragma unroll 4
    for (int i = 0; i < CHUNK; i += 16) {
        const int lr = i + rsub;
        float4 kv = kc4[(size_t)(row0 + lr) * 16 + seg];
        float4 qv = q4_sh[seg];
        float s = kv.x * qv.x + kv.y * qv.y + kv.z * qv.z + kv.w * qv.w;
        s += __shfl_xor_sync(0xffffffffu, s, 8);
        s += __shfl_xor_sync(0xffffffffu, s, 4);
        s += __shfl_xor_sync(0xffffffffu, s, 2);
        s += __shfl_xor_sync(0xffffffffu, s, 1);
        if (seg == 0) {
            float lg = s * inv_tc;
            logit_sh[lr] = lg;
            out_logit[(size_t)b * LL + row0 + lr] = lg;
            lmax = fmaxf(lmax, lg);
        }
    }

    // block-reduce max
    red[t] = lmax;
    __syncthreads();
    for (int off = 128; off > 0; off >>= 1) {
        if (t < off) red[t] = fmaxf(red[t], red[t + off]);
        __syncthreads();
    }
    const float m = red[0];
    __syncthreads();

    // ---- Pass 2a: exp once per logit, stage weights in SMEM, local sum ----
    float ls = 0.0f;
    for (int idx = t; idx < CHUNK; idx += 256) {
        float w = __expf(logit_sh[idx] - m);
        logit_sh[idx] = w;
        ls += w;
    }
    red[t] = ls;
    __syncthreads();
    for (int off = 128; off > 0; off >>= 1) {
        if (t < off) red[t] += red[t + off];
        __syncthreads();
    }
    const float s_tot = red[0];
    __syncthreads();

    // ---- Pass 2b: partial weighted v sum. 4 groups of 64 threads; thread
    // owns dim d = t&63, group g owns rows g, g+4, ... ----
    {
        const int d = t & 63;
        const int g = t >> 6;
        const float* vb = v + ((size_t)b * LL + row0) * DD;
        float acc = 0.0f;
        #pragma unroll 8
        for (int r = g; r < CHUNK; r += 4)
            acc += logit_sh[r] * vb[(size_t)r * DD + d];

        red[t] = acc;
        __syncthreads();
        if (t < 64) {
            float tot = red[t] + red[t + 64] + red[t + 128] + red[t + 192];
            g_partial_acc[((size_t)b * NSPLIT + c) * DD + t] = tot;
        }
        if (t == 0) {
            g_partial_m[b * NSPLIT + c] = m;
            g_partial_s[b * NSPLIT + c] = s_tot;
        }
    }
}

// ---------------------------------------------------------------------------
// Kernel C (fused combine + diffuse):
//   attn[b][:] merged from NSPLIT partials (per block, L2-hot, trivial),
//   gate = sigmoid(q.kd/td); out[b,l,:] = gate * attn[b,:].
// grid (L/256, B), 256 threads. float4 lanes: 16 lanes cover one row;
// each warp handles 2 rows per iteration via half-warp groups.
// ---------------------------------------------------------------------------
__global__ void __launch_bounds__(256)
diffuse_kernel(const float* __restrict__ q,
               const float* __restrict__ kd,
               const float* __restrict__ td,
               float* __restrict__ out)
{
    __shared__ float attn_sh[DD];
    __shared__ float4 q4_sh[16];

    const int b = blockIdx.y;
    const int t = threadIdx.x;

    // --- combine partials -> attn_sh (threads 0..63) ---
    if (t < DD) {
        const int d = t;
        float M = -FLT_MAX;
        float ms[NSPLIT];
        #pragma unroll
        for (int i = 0; i < NSPLIT; i++) {
            ms[i] = g_partial_m[b * NSPLIT + i];
            M = fmaxf(M, ms[i]);
        }
        float S = 0.0f, num = 0.0f;
        #pragma unroll
        for (int i = 0; i < NSPLIT; i++) {
            float e = __expf(ms[i] - M);
            S   += g_partial_s[b * NSPLIT + i] * e;
            num += g_partial_acc[((size_t)b * NSPLIT + i) * DD + d] * e;
        }
        attn_sh[d] = num / S;
    }
    if (t < 16) q4_sh[t] = ((const float4*)(q + b * DD))[t];
    __syncthreads();

    const float inv_td = 1.0f / *td;
    const int half = t >> 4;          // half-warp id within block (0..15)
    const int seg  = t & 15;          // float4 segment within row
    const float4 qv = q4_sh[seg];
    const float4 av = ((const float4*)attn_sh)[seg];

    const int row0 = blockIdx.x * 256;
    const float4* kd4 = (const float4*)(kd + (size_t)b * LL * DD);
    float4* o4 = (float4*)(out + (size_t)b * LL * DD);

    #pragma unroll 4
    for (int i = 0; i < 256; i += 16) {
        const int r = row0 + i + half;
        float4 kv = kd4[(size_t)r * 16 + seg];
        float s = kv.x * qv.x + kv.y * qv.y + kv.z * qv.z + kv.w * qv.w;
        // reduce within each 16-lane half-warp
        s += __shfl_xor_sync(0xffffffffu, s, 8);
        s += __shfl_xor_sync(0xffffffffu, s, 4);
        s += __shfl_xor_sync(0xffffffffu, s, 2);
        s += __shfl_xor_sync(0xffffffffu, s, 1);
        float gate = 1.0f / (1.0f + __expf(-s * inv_td));
        o4[(size_t)r * 16 + seg] =
            make_float4(gate * av.x, gate * av.y, gate * av.z, gate * av.w);
    }
}

// ---------------------------------------------------------------------------
extern "C" void kernel_launch(void* const* d_in, const int* in_sizes, int n_in,
                              void* d_out, int out_size)
{
    const float* q  = (const float*)d_in[0];
    const float* kc = (const float*)d_in[1];
    const float* kd = (const float*)d_in[2];
    const float* v  = (const float*)d_in[3];
    const float* tc = (const float*)d_in[4];
    const float* td = (const float*)d_in[5];

    float* out_main  = (float*)d_out;                         // [B, L, D]
    float* out_logit = (float*)d_out + (size_t)BB * LL * DD;  // [B, L]

    collect_partials_kernel<<<dim3(NSPLIT, BB), 256>>>(q, kc, v, tc, out_logit);
    diffuse_kernel<<<dim3(LL / 256, BB), 256>>>(q, kd, td, out_main);
}

// round 5
// speedup vs baseline: 1.0833x; 1.0833x over previous
#include <cuda_runtime.h>
#include <float.h>

#define BB 64
#define LL 8192
#define DD 64
#define NSPLIT 32
#define CHUNK (LL / NSPLIT)   // 256

// Scratch (device mallocs forbidden)
__device__ float g_partial_acc[BB * NSPLIT * DD];
__device__ float g_partial_m[BB * NSPLIT];
__device__ float g_partial_s[BB * NSPLIT];

// ---------------------------------------------------------------------------
// Kernel A: per (batch, 256-row chunk) — logits + softmax partials + partial
// exp-weighted v accumulation. No shuffles: independent coalesced loads ->
// SMEM partial dots -> per-thread row reduce.
// grid (NSPLIT, B), 256 threads.
// ---------------------------------------------------------------------------
__global__ void __launch_bounds__(256)
collect_partials_kernel(const float* __restrict__ q,
                        const float* __restrict__ kc,
                        const float* __restrict__ v,
                        const float* __restrict__ tc,
                        float* __restrict__ out_logit)
{
    __shared__ float  psum[CHUNK * 17];   // [row][seg], stride 17: conflict-free
    __shared__ float  w_sh[CHUNK];        // exp-weights
    __shared__ float  red[256];
    __shared__ float4 q4_sh[16];

    const int t = threadIdx.x;
    const int c = blockIdx.x;
    const int b = blockIdx.y;
    const int row0 = c * CHUNK;

    if (t < 16) q4_sh[t] = ((const float4*)(q + b * DD))[t];
    __syncthreads();

    const float inv_tc = 1.0f / *tc;
    const int seg  = t & 15;     // fixed float4 segment for this thread
    const int rsub = t >> 4;     // row sub-index
    const float4 qv = q4_sh[seg];

    // ---- Phase 1: 16 independent coalesced loads, partial dots to SMEM ----
    const float4* kc4 = (const float4*)(kc + (size_t)b * LL * DD);
    #pragma unroll
    for (int i = 0; i < 16; i++) {
        const int row = i * 16 + rsub;
        float4 kv = kc4[(size_t)(row0 + row) * 16 + seg];
        psum[row * 17 + seg] = kv.x * qv.x + kv.y * qv.y + kv.z * qv.z + kv.w * qv.w;
    }
    __syncthreads();

    // ---- Phase 2: per-thread row reduce -> logit; write logit output ----
    float s = 0.0f;
    #pragma unroll
    for (int j = 0; j < 16; j++) s += psum[t * 17 + j];
    const float lg = s * inv_tc;
    out_logit[(size_t)b * LL + row0 + t] = lg;

    // block max
    red[t] = lg;
    __syncthreads();
    for (int off = 128; off > 0; off >>= 1) {
        if (t < off) red[t] = fmaxf(red[t], red[t + off]);
        __syncthreads();
    }
    const float m = red[0];
    __syncthreads();

    // weights + block sum
    const float w = __expf(lg - m);
    w_sh[t] = w;
    red[t] = w;
    __syncthreads();
    for (int off = 128; off > 0; off >>= 1) {
        if (t < off) red[t] += red[t + off];
        __syncthreads();
    }
    const float s_tot = red[0];
    __syncthreads();

    // ---- Phase 3: weighted v partial sum. d = t&63 fixed; group g of 64
    // threads owns rows g, g+4, ... (coalesced 1KB per iteration). ----
    {
        const int d = t & 63;
        const int g = t >> 6;
        const float* vb = v + ((size_t)b * LL + row0) * DD;
        float acc = 0.0f;
        #pragma unroll 8
        for (int r = g; r < CHUNK; r += 4)
            acc += w_sh[r] * vb[(size_t)r * DD + d];

        red[t] = acc;
        __syncthreads();
        if (t < 64) {
            float tot = red[t] + red[t + 64] + red[t + 128] + red[t + 192];
            g_partial_acc[((size_t)b * NSPLIT + c) * DD + t] = tot;
        }
        if (t == 0) {
            g_partial_m[b * NSPLIT + c] = m;
            g_partial_s[b * NSPLIT + c] = s_tot;
        }
    }
}

// ---------------------------------------------------------------------------
// Kernel C (fused combine + diffuse), shuffle-free:
//   attn merged from partials; phase 1: independent loads -> SMEM partial
//   dots; phase 2: per-thread gate; phase 3: pure streaming store.
// grid (L/256, B), 256 threads.
// ---------------------------------------------------------------------------
__global__ void __launch_bounds__(256)
diffuse_kernel(const float* __restrict__ q,
               const float* __restrict__ kd,
               const float* __restrict__ td,
               float* __restrict__ out)
{
    __shared__ float  psum[256 * 17];
    __shared__ float  gate_sh[256];
    __shared__ float  attn_sh[DD];
    __shared__ float4 q4_sh[16];

    const int b = blockIdx.y;
    const int t = threadIdx.x;
    const int row0 = blockIdx.x * 256;

    // --- combine partials -> attn_sh (threads 0..63; L2-hot) ---
    if (t < DD) {
        const int d = t;
        float M = -FLT_MAX;
        #pragma unroll
        for (int i = 0; i < NSPLIT; i++)
            M = fmaxf(M, g_partial_m[b * NSPLIT + i]);
        float S = 0.0f, num = 0.0f;
        #pragma unroll
        for (int i = 0; i < NSPLIT; i++) {
            float e = __expf(g_partial_m[b * NSPLIT + i] - M);
            S   += g_partial_s[b * NSPLIT + i] * e;
            num += g_partial_acc[((size_t)b * NSPLIT + i) * DD + d] * e;
        }
        attn_sh[d] = num / S;
    }
    if (t < 16) q4_sh[t] = ((const float4*)(q + b * DD))[t];
    __syncthreads();

    const float inv_td = 1.0f / *td;
    const int seg  = t & 15;
    const int rsub = t >> 4;
    const float4 qv = q4_sh[seg];
    const float4 av = ((const float4*)attn_sh)[seg];

    // ---- Phase 1: 16 independent coalesced kd loads, partial dots ----
    const float4* kd4 = (const float4*)(kd + (size_t)b * LL * DD);
    #pragma unroll
    for (int i = 0; i < 16; i++) {
        const int row = i * 16 + rsub;
        float4 kv = kd4[(size_t)(row0 + row) * 16 + seg];
        psum[row * 17 + seg] = kv.x * qv.x + kv.y * qv.y + kv.z * qv.z + kv.w * qv.w;
    }
    __syncthreads();

    // ---- Phase 2: per-thread gate ----
    {
        float s = 0.0f;
        #pragma unroll
        for (int j = 0; j < 16; j++) s += psum[t * 17 + j];
        gate_sh[t] = 1.0f / (1.0f + __expf(-s * inv_td));
    }
    __syncthreads();

    // ---- Phase 3: pure streaming store ----
    float4* o4 = (float4*)(out + (size_t)b * LL * DD);
    #pragma unroll
    for (int i = 0; i < 16; i++) {
        const int row = i * 16 + rsub;
        const float g = gate_sh[row];
        o4[(size_t)(row0 + row) * 16 + seg] =
            make_float4(g * av.x, g * av.y, g * av.z, g * av.w);
    }
}

// ---------------------------------------------------------------------------
extern "C" void kernel_launch(void* const* d_in, const int* in_sizes, int n_in,
                              void* d_out, int out_size)
{
    const float* q  = (const float*)d_in[0];
    const float* kc = (const float*)d_in[1];
    const float* kd = (const float*)d_in[2];
    const float* v  = (const float*)d_in[3];
    const float* tc = (const float*)d_in[4];
    const float* td = (const float*)d_in[5];

    float* out_main  = (float*)d_out;                         // [B, L, D]
    float* out_logit = (float*)d_out + (size_t)BB * LL * DD;  // [B, L]

    collect_partials_kernel<<<dim3(NSPLIT, BB), 256>>>(q, kc, v, tc, out_logit);
    diffuse_kernel<<<dim3(LL / 256, BB), 256>>>(q, kd, td, out_main);
}